// round 16
// baseline (speedup 1.0000x reference)
#include <cuda_runtime.h>
#include <cstdint>
#include <math.h>

#define NUM_ITEMS 6714
#define N2 3357            // float2 per row
#define TAIL2 29           // N2 - 13*256
#define RANK 100
#define NTHREADS 256
#define NWARPS 8
#define KPT 14
#define THRESH_F 2.0f      // count(>=2.0) ~ 153 +/- 12 per row for this data
#define CAND_CAP 1024
#define STOPF 156
#define MAXITER 40

__device__ __forceinline__ uint32_t flip_f32(uint32_t s) {
    return s ^ ((s & 0x80000000u) ? 0xFFFFFFFFu : 0x80000000u);
}
__device__ __forceinline__ float unflip_f32(uint32_t k) {
    uint32_t s = (k & 0x80000000u) ? (k ^ 0x80000000u) : ~k;
    return __uint_as_float(s);
}
// Bin nondecreasing in packed candidate (~key,idx) i.e. nonincreasing in key.
// Monotone for ALL keys (ends clamp) -> correct for arbitrary inputs.
// Dense candidate region (values 2.0..4.0) spreads across all 256 bins.
__device__ __forceinline__ uint32_t bin_of_key(uint32_t key) {
    uint32_t b = (key >= 0xC0000000u) ? min(255u, (key - 0xC0000000u) >> 15) : 0u;
    return 255u - b;
}

struct Shared {
    alignas(16) unsigned long long cand[CAND_CAP]; // bin-sorted candidates
    uint32_t hist[256];
    uint32_t pfx[256];
    uint32_t binpos[256];
    uint32_t wred[NWARPS];
    uint32_t wred2[2][NWARPS];
    uint32_t cnt0;
    int found;
    float labelval;
};

// Exclusive scan of hist -> pfx, binpos; returns total. Entry: hist ready + synced.
__device__ __forceinline__ uint32_t scan_hist(Shared& s, int tid, int lane, int wid) {
    uint32_t hv = s.hist[tid];
    uint32_t ic = hv;
    #pragma unroll
    for (int o = 1; o < 32; o <<= 1) {
        uint32_t u = __shfl_up_sync(0xFFFFFFFFu, ic, o);
        if (lane >= o) ic += u;
    }
    if (lane == 31) s.wred[wid] = ic;
    __syncthreads();
    uint32_t wadd = 0, tot = 0;
    #pragma unroll
    for (int w = 0; w < NWARPS; ++w) {
        uint32_t t = s.wred[w];
        tot += t;
        if (w < wid) wadd += t;
    }
    uint32_t excl = wadd + ic - hv;
    s.pfx[tid] = excl;
    s.binpos[tid] = excl;
    __syncthreads();
    return tot;
}

__global__ __launch_bounds__(NTHREADS, 6) void logit_selector_kernel(
    const float* __restrict__ output,
    const int* __restrict__ labels,
    float* __restrict__ out_vals,
    float* __restrict__ out_labels)
{
    __shared__ Shared s;

    const int row  = blockIdx.x;
    const int tid  = threadIdx.x;
    const int lane = tid & 31;
    const int wid  = tid >> 5;
    const float* row_ptr = output + (size_t)row * NUM_ITEMS;
    const float2* row2 = reinterpret_cast<const float2*>(row_ptr);
    const int label = labels[row];

    // ---- front-batched load: 13 unchecked + 1 checked float2 (MLP ~14) ----
    float2 v[KPT];
    #pragma unroll
    for (int j = 0; j < KPT - 1; ++j)
        v[j] = row2[tid + j * NTHREADS];
    if (tid < TAIL2) v[KPT - 1] = row2[tid + (KPT - 1) * NTHREADS];
    else { v[KPT - 1].x = -INFINITY; v[KPT - 1].y = -INFINITY; }

    if (tid == 0) { s.found = -1; s.labelval = row_ptr[label]; }
    s.hist[tid] = 0u;
    __syncthreads();

    // ---- branch-free hit-mask build (v[] dies here: short live range) ----
    uint32_t mask = 0u;
    #pragma unroll
    for (int j = 0; j < KPT; ++j) {
        mask |= (v[j].x >= THRESH_F ? 1u : 0u) << (2 * j);
        mask |= (v[j].y >= THRESH_F ? 1u : 0u) << (2 * j + 1);
    }

    // ---- walk 1: histogram over set bits only (avg ~0.6/thread, L1 reload) ----
    {
        uint32_t m = mask;
        while (m) {
            uint32_t b = (uint32_t)__ffs(m) - 1u;
            m &= m - 1u;
            uint32_t idx = 2u * ((uint32_t)tid + (b >> 1) * NTHREADS) + (b & 1u);
            uint32_t key = flip_f32(__float_as_uint(row_ptr[idx]));
            atomicAdd(&s.hist[bin_of_key(key)], 1u);
        }
    }
    __syncthreads();

    uint32_t cntN = scan_hist(s, tid, lane, wid);

    if (cntN >= RANK && cntN <= CAND_CAP) {
        // ---- walk 2: scatter set bits straight into bin-sorted positions ----
        // Positions exact (< cntN <= CAND_CAP): no bounds checks needed.
        uint32_t m = mask;
        while (m) {
            uint32_t b = (uint32_t)__ffs(m) - 1u;
            m &= m - 1u;
            uint32_t idx = 2u * ((uint32_t)tid + (b >> 1) * NTHREADS) + (b & 1u);
            uint32_t key = flip_f32(__float_as_uint(row_ptr[idx]));
            uint32_t pos = atomicAdd(&s.binpos[bin_of_key(key)], 1u);
            s.cand[pos] = ((unsigned long long)(~key) << 32) | idx;
        }
        __syncthreads();
    } else {
        // ---- fallback: exact bit-narrowing reading global (never on this data) ----
        if (tid == 0) s.cnt0 = 0u;
        s.hist[tid] = 0u;
        __syncthreads();
        uint32_t pfx32 = 0u, k = RANK, cand = NUM_ITEMS;
        int sh = 31, iter = 0;
        while (cand > STOPF && sh >= 0 && iter < MAXITER) {
            const uint32_t t = (pfx32 << 1) | 1u;
            int c = 0;
            for (int i = tid; i < NUM_ITEMS; i += NTHREADS)
                c += ((flip_f32(__float_as_uint(row_ptr[i])) >> sh) == t);
            c = __reduce_add_sync(0xFFFFFFFFu, c);     // reconverged after loop
            if (lane == 0) s.wred2[iter & 1][wid] = (uint32_t)c;
            __syncthreads();
            uint32_t cnt1 = 0;
            #pragma unroll
            for (int w = 0; w < NWARPS; ++w) cnt1 += s.wred2[iter & 1][w];
            if (cnt1 >= k) { pfx32 = t; cand = cnt1; }
            else           { k -= cnt1; pfx32 <<= 1; cand -= cnt1; }
            --sh; ++iter;
        }
        const uint32_t tf = (sh >= 31) ? 0u : (pfx32 << (sh + 1));
        for (int i = tid; i < NUM_ITEMS; i += NTHREADS) {
            uint32_t key = flip_f32(__float_as_uint(row_ptr[i]));
            if (key >= tf) {
                uint32_t pos = atomicAdd(&s.cnt0, 1u);
                if (pos < CAND_CAP) {
                    s.cand[pos] = ((unsigned long long)(~key) << 32) | (uint32_t)i;
                    atomicAdd(&s.hist[bin_of_key(key)], 1u);
                }
            }
        }
        __syncthreads();
        cntN = min(s.cnt0, (uint32_t)CAND_CAP);

        // read staged, scan, scatter into bin-sorted order
        unsigned long long p[4];
        uint32_t bn[4];
        int nb = 0;
        #pragma unroll
        for (int i = 0; i < 4; ++i) {
            uint32_t c = (uint32_t)tid + (uint32_t)i * NTHREADS;
            if (c < cntN) {
                p[i] = s.cand[c];
                bn[i] = bin_of_key(~(uint32_t)(p[i] >> 32));
                ++nb;
            }
        }
        scan_hist(s, tid, lane, wid);   // internal syncs separate reads from writes
        #pragma unroll
        for (int i = 0; i < 4; ++i)
            if (i < nb) {
                uint32_t pos = atomicAdd(&s.binpos[bn[i]], 1u);
                if (pos < CAND_CAP) s.cand[pos] = p[i];
            }
        __syncthreads();
    }

    // ---- refine within bin + write outputs (exact u64 tie-break) ----
    float* out_row = out_vals + (size_t)row * RANK;
    #pragma unroll
    for (int i = 0; i < 4; ++i) {
        uint32_t c = (uint32_t)tid + (uint32_t)i * NTHREADS;
        if (c < cntN) {
            unsigned long long p64 = s.cand[c];
            uint32_t key = ~(uint32_t)(p64 >> 32);
            uint32_t b = bin_of_key(key);
            uint32_t base = s.pfx[b];
            uint32_t m = s.hist[b];
            uint32_t r = base;
            for (uint32_t t2 = 0; t2 < m; ++t2)
                r += (s.cand[base + t2] < p64);
            if (r < RANK) {
                int jj = (RANK - 1) - (int)r;
                out_row[jj] = unflip_f32(key);
                if ((uint32_t)p64 == (uint32_t)label)
                    s.found = jj;                      // unique writer
            }
        }
    }
    __syncthreads();

    if (tid == 0) {
        int found = s.found;
        if (found < 0) out_row[0] = s.labelval;        // substitute missing label
        out_labels[row] = (float)(found < 0 ? 0 : found);
    }
}

extern "C" void kernel_launch(void* const* d_in, const int* in_sizes, int n_in,
                              void* d_out, int out_size) {
    const float* output = (const float*)d_in[0];
    const int*   labels = (const int*)d_in[1];
    const int batch = in_sizes[1];

    float* out_vals   = (float*)d_out;
    float* out_labels = out_vals + (size_t)batch * RANK;

    logit_selector_kernel<<<batch, NTHREADS>>>(output, labels, out_vals, out_labels);
}

// round 17
// speedup vs baseline: 1.0493x; 1.0493x over previous
#include <cuda_runtime.h>
#include <cstdint>
#include <math.h>

#define NUM_ITEMS 6714
#define N2 3357            // float2 per row
#define TAIL2 29           // N2 - 13*256
#define RANK 100
#define NTHREADS 256
#define NWARPS 8
#define KPT 14
#define KHALF 7
#define THRESH_F 2.0f      // count(>=2.0) ~ 153 +/- 12 per row for this data
#define CAND_CAP 1024
#define STOPF 156
#define MAXITER 40

__device__ __forceinline__ uint32_t flip_f32(uint32_t s) {
    return s ^ ((s & 0x80000000u) ? 0xFFFFFFFFu : 0x80000000u);
}
__device__ __forceinline__ float unflip_f32(uint32_t k) {
    uint32_t s = (k & 0x80000000u) ? (k ^ 0x80000000u) : ~k;
    return __uint_as_float(s);
}
// Bin nondecreasing in packed candidate (~key,idx) i.e. nonincreasing in key.
// Monotone for ALL keys (ends clamp) -> correct for arbitrary inputs.
// Dense candidate region (values 2.0..4.0) spreads across all 256 bins.
__device__ __forceinline__ uint32_t bin_of_key(uint32_t key) {
    uint32_t b = (key >= 0xC0000000u) ? min(255u, (key - 0xC0000000u) >> 15) : 0u;
    return 255u - b;
}

struct Shared {
    alignas(16) unsigned long long cand[CAND_CAP]; // bin-sorted candidates
    uint32_t hist[256];
    uint32_t pfx[256];
    uint32_t binpos[256];
    uint32_t wred[NWARPS];
    uint32_t wred2[2][NWARPS];
    uint32_t cnt0;
    int found;
    float labelval;
};

// Exclusive scan of hist -> pfx, binpos; returns total. Entry: hist ready + synced.
__device__ __forceinline__ uint32_t scan_hist(Shared& s, int tid, int lane, int wid) {
    uint32_t hv = s.hist[tid];
    uint32_t ic = hv;
    #pragma unroll
    for (int o = 1; o < 32; o <<= 1) {
        uint32_t u = __shfl_up_sync(0xFFFFFFFFu, ic, o);
        if (lane >= o) ic += u;
    }
    if (lane == 31) s.wred[wid] = ic;
    __syncthreads();
    uint32_t wadd = 0, tot = 0;
    #pragma unroll
    for (int w = 0; w < NWARPS; ++w) {
        uint32_t t = s.wred[w];
        tot += t;
        if (w < wid) wadd += t;
    }
    uint32_t excl = wadd + ic - hv;
    s.pfx[tid] = excl;
    s.binpos[tid] = excl;
    __syncthreads();
    return tot;
}

__global__ __launch_bounds__(NTHREADS, 8) void logit_selector_kernel(
    const float* __restrict__ output,
    const int* __restrict__ labels,
    float* __restrict__ out_vals,
    float* __restrict__ out_labels)
{
    __shared__ Shared s;

    const int row  = blockIdx.x;
    const int tid  = threadIdx.x;
    const int lane = tid & 31;
    const int wid  = tid >> 5;
    const float* row_ptr = output + (size_t)row * NUM_ITEMS;
    const float2* row2 = reinterpret_cast<const float2*>(row_ptr);
    const int label = labels[row];

    if (tid == 0) { s.found = -1; s.labelval = row_ptr[label]; }
    s.hist[tid] = 0u;

    // ---- half-batch 1: 7 float2 in flight, convert to mask bits, regs die ----
    uint32_t mask = 0u;
    {
        float2 v[KHALF];
        #pragma unroll
        for (int j = 0; j < KHALF; ++j)
            v[j] = row2[tid + j * NTHREADS];
        #pragma unroll
        for (int j = 0; j < KHALF; ++j) {
            mask |= (v[j].x >= THRESH_F ? 1u : 0u) << (2 * j);
            mask |= (v[j].y >= THRESH_F ? 1u : 0u) << (2 * j + 1);
        }
    }
    asm volatile("" ::: "memory");   // keep batch 2 loads below batch 1 consumption

    // ---- half-batch 2: remaining 6 unchecked + 1 checked float2 ----
    {
        float2 v[KHALF];
        #pragma unroll
        for (int j = 0; j < KHALF - 1; ++j)
            v[j] = row2[tid + (KHALF + j) * NTHREADS];
        if (tid < TAIL2) v[KHALF - 1] = row2[tid + (KPT - 1) * NTHREADS];
        else { v[KHALF - 1].x = -INFINITY; v[KHALF - 1].y = -INFINITY; }
        #pragma unroll
        for (int j = 0; j < KHALF; ++j) {
            mask |= (v[j].x >= THRESH_F ? 1u : 0u) << (2 * (KHALF + j));
            mask |= (v[j].y >= THRESH_F ? 1u : 0u) << (2 * (KHALF + j) + 1);
        }
    }
    __syncthreads();                  // hist zero + label val visible

    // ---- walk 1: histogram over set bits only (avg ~0.6/thread, L1 reload) ----
    {
        uint32_t m = mask;
        while (m) {
            uint32_t b = (uint32_t)__ffs(m) - 1u;
            m &= m - 1u;
            uint32_t idx = 2u * ((uint32_t)tid + (b >> 1) * NTHREADS) + (b & 1u);
            uint32_t key = flip_f32(__float_as_uint(row_ptr[idx]));
            atomicAdd(&s.hist[bin_of_key(key)], 1u);
        }
    }
    __syncthreads();

    uint32_t cntN = scan_hist(s, tid, lane, wid);

    if (cntN >= RANK && cntN <= CAND_CAP) {
        // ---- walk 2: scatter set bits straight into bin-sorted positions ----
        uint32_t m = mask;
        while (m) {
            uint32_t b = (uint32_t)__ffs(m) - 1u;
            m &= m - 1u;
            uint32_t idx = 2u * ((uint32_t)tid + (b >> 1) * NTHREADS) + (b & 1u);
            uint32_t key = flip_f32(__float_as_uint(row_ptr[idx]));
            uint32_t pos = atomicAdd(&s.binpos[bin_of_key(key)], 1u);
            s.cand[pos] = ((unsigned long long)(~key) << 32) | idx;
        }
        __syncthreads();
    } else {
        // ---- fallback: exact bit-narrowing reading global (never on this data) ----
        if (tid == 0) s.cnt0 = 0u;
        s.hist[tid] = 0u;
        __syncthreads();
        uint32_t pfx32 = 0u, k = RANK, cand = NUM_ITEMS;
        int sh = 31, iter = 0;
        while (cand > STOPF && sh >= 0 && iter < MAXITER) {
            const uint32_t t = (pfx32 << 1) | 1u;
            int c = 0;
            for (int i = tid; i < NUM_ITEMS; i += NTHREADS)
                c += ((flip_f32(__float_as_uint(row_ptr[i])) >> sh) == t);
            c = __reduce_add_sync(0xFFFFFFFFu, c);     // reconverged after loop
            if (lane == 0) s.wred2[iter & 1][wid] = (uint32_t)c;
            __syncthreads();
            uint32_t cnt1 = 0;
            #pragma unroll
            for (int w = 0; w < NWARPS; ++w) cnt1 += s.wred2[iter & 1][w];
            if (cnt1 >= k) { pfx32 = t; cand = cnt1; }
            else           { k -= cnt1; pfx32 <<= 1; cand -= cnt1; }
            --sh; ++iter;
        }
        const uint32_t tf = (sh >= 31) ? 0u : (pfx32 << (sh + 1));
        for (int i = tid; i < NUM_ITEMS; i += NTHREADS) {
            uint32_t key = flip_f32(__float_as_uint(row_ptr[i]));
            if (key >= tf) {
                uint32_t pos = atomicAdd(&s.cnt0, 1u);
                if (pos < CAND_CAP) {
                    s.cand[pos] = ((unsigned long long)(~key) << 32) | (uint32_t)i;
                    atomicAdd(&s.hist[bin_of_key(key)], 1u);
                }
            }
        }
        __syncthreads();
        cntN = min(s.cnt0, (uint32_t)CAND_CAP);

        // read staged, scan, scatter into bin-sorted order
        unsigned long long p[4];
        uint32_t bn[4];
        int nb = 0;
        #pragma unroll
        for (int i = 0; i < 4; ++i) {
            uint32_t c = (uint32_t)tid + (uint32_t)i * NTHREADS;
            if (c < cntN) {
                p[i] = s.cand[c];
                bn[i] = bin_of_key(~(uint32_t)(p[i] >> 32));
                ++nb;
            }
        }
        scan_hist(s, tid, lane, wid);   // internal syncs separate reads from writes
        #pragma unroll
        for (int i = 0; i < 4; ++i)
            if (i < nb) {
                uint32_t pos = atomicAdd(&s.binpos[bn[i]], 1u);
                if (pos < CAND_CAP) s.cand[pos] = p[i];
            }
        __syncthreads();
    }

    // ---- refine within bin + write outputs (exact u64 tie-break) ----
    float* out_row = out_vals + (size_t)row * RANK;
    #pragma unroll
    for (int i = 0; i < 4; ++i) {
        uint32_t c = (uint32_t)tid + (uint32_t)i * NTHREADS;
        if (c < cntN) {
            unsigned long long p64 = s.cand[c];
            uint32_t key = ~(uint32_t)(p64 >> 32);
            uint32_t b = bin_of_key(key);
            uint32_t base = s.pfx[b];
            uint32_t m = s.hist[b];
            uint32_t r = base;
            for (uint32_t t2 = 0; t2 < m; ++t2)
                r += (s.cand[base + t2] < p64);
            if (r < RANK) {
                int jj = (RANK - 1) - (int)r;
                out_row[jj] = unflip_f32(key);
                if ((uint32_t)p64 == (uint32_t)label)
                    s.found = jj;                      // unique writer
            }
        }
    }
    __syncthreads();

    if (tid == 0) {
        int found = s.found;
        if (found < 0) out_row[0] = s.labelval;        // substitute missing label
        out_labels[row] = (float)(found < 0 ? 0 : found);
    }
}

extern "C" void kernel_launch(void* const* d_in, const int* in_sizes, int n_in,
                              void* d_out, int out_size) {
    const float* output = (const float*)d_in[0];
    const int*   labels = (const int*)d_in[1];
    const int batch = in_sizes[1];

    float* out_vals   = (float*)d_out;
    float* out_labels = out_vals + (size_t)batch * RANK;

    logit_selector_kernel<<<batch, NTHREADS>>>(output, labels, out_vals, out_labels);
}